// round 16
// baseline (speedup 1.0000x reference)
#include <cuda_runtime.h>
#include <cuda_fp16.h>
#include <math.h>
#include <stdint.h>

#define Bn 8
#define Ln 2048
#define Cn 512
#define Hn 8
#define Dn 64
#define FFn 2048
#define BLn (Bn*Ln)          /* 16384 */
#define BHn (Bn*Hn)          /* 64    */
#define BHLn (BHn*Ln)        /* 131072*/
#define KVCHUNKS 8

// ---------------- scratch (static device globals; no allocation) ----------------
static __device__ __align__(16) __half g_xbufh[BLn*Cn];
static __device__ __align__(16) __half g_lnh[BLn*Cn];
static __device__ __align__(16) __half g_qkvh[(long)BLn*1536];
static __device__ __align__(16) __half g_q2h[BHLn*Dn];
static __device__ __align__(16) __half g_k2h[BHLn*Dn];
static __device__ __align__(16) __half g_kvpart[KVCHUNKS*BHn*Dn*Dn];
static __device__ __align__(16) float  g_kmpart[KVCHUNKS*BHn*Dn];
static __device__ __align__(16) __half g_kvT2h[BHn*72*64];   // B^T tiles + km row + zero pad
static __device__ __align__(16) __half g_spinh[BLn*Cn];
static __device__ __align__(16) __half g_hb[BLn*Cn];
static __device__ __align__(16) __half g_ffnh[(long)BLn*FFn];
// weights (half), prepared once per call
static __device__ __align__(16) __half g_qkvTh[1536*512];
static __device__ __align__(16) __half g_w1Th[2048*512];
static __device__ __align__(16) __half g_w2Th[512*2048];
static __device__ __align__(16) __half g_wtT2h[1024*1536];
static __device__ __align__(16) float  g_bias2[1024];
static __device__ __align__(16) float  g_bias3[1536];

// ---------------- PTX helpers ----------------
__device__ __forceinline__ uint32_t smem_u32(const void* p) {
    uint32_t a;
    asm("{ .reg .u64 t; cvta.to.shared.u64 t, %1; cvt.u32.u64 %0, t; }" : "=r"(a) : "l"(p));
    return a;
}
__device__ __forceinline__ void cpasync16(uint32_t saddr, const void* g) {
    asm volatile("cp.async.cg.shared.global [%0], [%1], 16;" :: "r"(saddr), "l"(g) : "memory");
}
__device__ __forceinline__ void cpasync16z(uint32_t saddr, const void* g, uint32_t sz) {
    asm volatile("cp.async.cg.shared.global [%0], [%1], 16, %2;"
                 :: "r"(saddr), "l"(g), "r"(sz) : "memory");
}
#define CP_COMMIT() asm volatile("cp.async.commit_group;" ::: "memory")
#define CP_WAIT1()  asm volatile("cp.async.wait_group 1;" ::: "memory")

__device__ __forceinline__ void ldsm4(uint32_t* r, uint32_t addr) {
    asm volatile("ldmatrix.sync.aligned.m8n8.x4.shared.b16 {%0,%1,%2,%3}, [%4];"
        : "=r"(r[0]), "=r"(r[1]), "=r"(r[2]), "=r"(r[3]) : "r"(addr));
}
__device__ __forceinline__ void ldsm2(uint32_t* r, uint32_t addr) {
    asm volatile("ldmatrix.sync.aligned.m8n8.x2.shared.b16 {%0,%1}, [%2];"
        : "=r"(r[0]), "=r"(r[1]) : "r"(addr));
}
__device__ __forceinline__ void mma_f16(float* c, const uint32_t* a, const uint32_t* b) {
    asm volatile(
        "mma.sync.aligned.m16n8k16.row.col.f32.f16.f16.f32 "
        "{%0,%1,%2,%3}, {%4,%5,%6,%7}, {%8,%9}, {%0,%1,%2,%3};"
        : "+f"(c[0]), "+f"(c[1]), "+f"(c[2]), "+f"(c[3])
        : "r"(a[0]), "r"(a[1]), "r"(a[2]), "r"(a[3]), "r"(b[0]), "r"(b[1]));
}

// ---------------- small helpers ----------------
__device__ __forceinline__ float elu1f(float x) { return x > 0.0f ? x + 1.0f : __expf(x); }

// ---------------- one-shot weight prep ----------------
#define PW_S0 524288L
#define PW_S1 (PW_S0 + 262144L)
#define PW_S2 (PW_S1 + 1048576L)
#define PW_S3 (PW_S2 + 1048576L)
#define PW_S4 (PW_S3 + 1572864L)
#define PW_TOT (PW_S4 + 1536L)
__global__ void prep_weights_kernel(const float* __restrict__ qk_w, const float* __restrict__ v_w,
                                    const float* __restrict__ w1, const float* __restrict__ w2,
                                    const float* __restrict__ sp_cw,
                                    const float* __restrict__ qk_b, const float* __restrict__ v_b,
                                    const float* __restrict__ sp_cb,
                                    __half* __restrict__ qkvT, __half* __restrict__ w1T,
                                    __half* __restrict__ w2T, __half* __restrict__ wtT2,
                                    float* __restrict__ bias2, float* __restrict__ bias3) {
    long idx = (long)blockIdx.x * blockDim.x + threadIdx.x;
    if (idx < PW_S0) {
        int k = (int)(idx & 511), n = (int)(idx >> 9);
        qkvT[idx] = __float2half_rn(qk_w[(long)k * 1024 + n]);
    } else if (idx < PW_S1) {
        long i = idx - PW_S0;
        int k = (int)(i & 511), n = (int)(i >> 9);
        qkvT[idx] = __float2half_rn(v_w[(long)k * 512 + n]);
    } else if (idx < PW_S2) {
        long i = idx - PW_S1;
        int k = (int)(i & 511), n = (int)(i >> 9);
        w1T[i] = __float2half_rn(w1[(long)k * 2048 + n]);
    } else if (idx < PW_S3) {
        long i = idx - PW_S2;
        int k = (int)(i & 2047), n = (int)(i >> 11);
        w2T[i] = __float2half_rn(w2[(long)k * 512 + n]);
    } else if (idx < PW_S4) {
        long i = idx - PW_S3;
        int kk = (int)(i % 1536), n2 = (int)(i / 1536);
        int co = (n2 & 1) * 512 + (n2 >> 1);
        int k  = kk >> 9, ci = kk & 511;
        wtT2[i] = __float2half_rn(sp_cw[co * 1536 + ci * 3 + k]);
        if (kk == 0) bias2[n2] = sp_cb[co];
    } else if (idx < PW_TOT) {
        int j = (int)(idx - PW_S4);
        bias3[j] = (j < 1024) ? qk_b[j] : v_b[j - 1024];
    }
}

// ---------------- LayerNorm, float input -> half out ----------------
__global__ void ln_h_kernel(const float* __restrict__ in, const float* __restrict__ gam,
                            const float* __restrict__ bet, __half* __restrict__ out) {
    int row = blockIdx.x;
    int t = threadIdx.x;
    const float4 v = ((const float4*)(in + (long)row * Cn))[t];
    float s  = v.x + v.y + v.z + v.w;
    float sq = v.x*v.x + v.y*v.y + v.z*v.z + v.w*v.w;
    #pragma unroll
    for (int o = 16; o; o >>= 1) {
        s  += __shfl_xor_sync(0xFFFFFFFFu, s,  o);
        sq += __shfl_xor_sync(0xFFFFFFFFu, sq, o);
    }
    __shared__ float ss[4], ssq[4];
    if ((t & 31) == 0) { ss[t >> 5] = s; ssq[t >> 5] = sq; }
    __syncthreads();
    s  = ss[0] + ss[1] + ss[2] + ss[3];
    sq = ssq[0] + ssq[1] + ssq[2] + ssq[3];
    float mu   = s * (1.0f / Cn);
    float var  = sq * (1.0f / Cn) - mu * mu;
    float rstd = rsqrtf(var + 1e-5f);
    float4 g4 = ((const float4*)gam)[t];
    float4 b4 = ((const float4*)bet)[t];
    __half2* o = (__half2*)(out + (long)row * Cn);
    o[t * 2]     = __floats2half2_rn((v.x - mu) * rstd * g4.x + b4.x,
                                     (v.y - mu) * rstd * g4.y + b4.y);
    o[t * 2 + 1] = __floats2half2_rn((v.z - mu) * rstd * g4.z + b4.z,
                                     (v.w - mu) * rstd * g4.w + b4.w);
}

// ---------------- LayerNorm, half input -> half out ----------------
__global__ void ln_hh_kernel(const __half* __restrict__ in, const float* __restrict__ gam,
                             const float* __restrict__ bet, __half* __restrict__ out) {
    int row = blockIdx.x;
    int t = threadIdx.x;
    uint2 raw = ((const uint2*)(in + (long)row * Cn))[t];
    float2 p0 = __half22float2(*(__half2*)&raw.x);
    float2 p1 = __half22float2(*(__half2*)&raw.y);
    float4 v = {p0.x, p0.y, p1.x, p1.y};
    float s  = v.x + v.y + v.z + v.w;
    float sq = v.x*v.x + v.y*v.y + v.z*v.z + v.w*v.w;
    #pragma unroll
    for (int o = 16; o; o >>= 1) {
        s  += __shfl_xor_sync(0xFFFFFFFFu, s,  o);
        sq += __shfl_xor_sync(0xFFFFFFFFu, sq, o);
    }
    __shared__ float ss[4], ssq[4];
    if ((t & 31) == 0) { ss[t >> 5] = s; ssq[t >> 5] = sq; }
    __syncthreads();
    s  = ss[0] + ss[1] + ss[2] + ss[3];
    sq = ssq[0] + ssq[1] + ssq[2] + ssq[3];
    float mu   = s * (1.0f / Cn);
    float var  = sq * (1.0f / Cn) - mu * mu;
    float rstd = rsqrtf(var + 1e-5f);
    float4 g4 = ((const float4*)gam)[t];
    float4 b4 = ((const float4*)bet)[t];
    __half2* o = (__half2*)(out + (long)row * Cn);
    o[t * 2]     = __floats2half2_rn((v.x - mu) * rstd * g4.x + b4.x,
                                     (v.y - mu) * rstd * g4.y + b4.y);
    o[t * 2 + 1] = __floats2half2_rn((v.z - mu) * rstd * g4.z + b4.z,
                                     (v.w - mu) * rstd * g4.w + b4.w);
}

// ---------------- fused LN2 + LN3 (half in) ----------------
__global__ void ln2ln3_kernel(const __half* __restrict__ in,
                              const float* __restrict__ g2, const float* __restrict__ b2,
                              const float* __restrict__ g3, const float* __restrict__ b3,
                              __half* __restrict__ spin, __half* __restrict__ hb) {
    int row = blockIdx.x;
    int t = threadIdx.x;
    __shared__ float ss[4], ssq[4];
    uint2 raw = ((const uint2*)(in + (long)row * Cn))[t];
    float2 p0 = __half22float2(*(__half2*)&raw.x);
    float2 p1 = __half22float2(*(__half2*)&raw.y);
    float4 v = {p0.x, p0.y, p1.x, p1.y};
    float s  = v.x + v.y + v.z + v.w;
    float sq = v.x*v.x + v.y*v.y + v.z*v.z + v.w*v.w;
    #pragma unroll
    for (int o = 16; o; o >>= 1) {
        s  += __shfl_xor_sync(0xFFFFFFFFu, s,  o);
        sq += __shfl_xor_sync(0xFFFFFFFFu, sq, o);
    }
    if ((t & 31) == 0) { ss[t >> 5] = s; ssq[t >> 5] = sq; }
    __syncthreads();
    s  = ss[0] + ss[1] + ss[2] + ss[3];
    sq = ssq[0] + ssq[1] + ssq[2] + ssq[3];
    float mu   = s * (1.0f / Cn);
    float var  = sq * (1.0f / Cn) - mu * mu;
    float rstd = rsqrtf(var + 1e-5f);
    float4 gg = ((const float4*)g2)[t];
    float4 bb = ((const float4*)b2)[t];
    float4 o1;
    o1.x = (v.x - mu) * rstd * gg.x + bb.x;
    o1.y = (v.y - mu) * rstd * gg.y + bb.y;
    o1.z = (v.z - mu) * rstd * gg.z + bb.z;
    o1.w = (v.w - mu) * rstd * gg.w + bb.w;
    __half2* sp = (__half2*)(spin + (long)row * Cn);
    sp[t * 2]     = __floats2half2_rn(o1.x, o1.y);
    sp[t * 2 + 1] = __floats2half2_rn(o1.z, o1.w);
    float s2  = o1.x + o1.y + o1.z + o1.w;
    float sq2 = o1.x*o1.x + o1.y*o1.y + o1.z*o1.z + o1.w*o1.w;
    #pragma unroll
    for (int o = 16; o; o >>= 1) {
        s2  += __shfl_xor_sync(0xFFFFFFFFu, s2,  o);
        sq2 += __shfl_xor_sync(0xFFFFFFFFu, sq2, o);
    }
    __syncthreads();
    if ((t & 31) == 0) { ss[t >> 5] = s2; ssq[t >> 5] = sq2; }
    __syncthreads();
    s2  = ss[0] + ss[1] + ss[2] + ss[3];
    sq2 = ssq[0] + ssq[1] + ssq[2] + ssq[3];
    float mu2   = s2 * (1.0f / Cn);
    float var2  = sq2 * (1.0f / Cn) - mu2 * mu2;
    float rstd2 = rsqrtf(var2 + 1e-5f);
    float4 g4 = ((const float4*)g3)[t];
    float4 b4 = ((const float4*)b3)[t];
    __half2* o = (__half2*)(hb + (long)row * Cn);
    o[t * 2]     = __floats2half2_rn((o1.x - mu2) * rstd2 * g4.x + b4.x,
                                     (o1.y - mu2) * rstd2 * g4.y + b4.y);
    o[t * 2 + 1] = __floats2half2_rn((o1.z - mu2) * rstd2 * g4.z + b4.z,
                                     (o1.w - mu2) * rstd2 * g4.w + b4.w);
}

// ---------------- qk post (R13 form, no launch-bounds): elu at smem fill, half2 FMA LePE ----------------
__global__ void qk_post_kernel(const __half* __restrict__ qkv,
                               const float* __restrict__ lw, const float* __restrict__ lb,
                               __half* __restrict__ q2, __half* __restrict__ k2) {
    int bh = blockIdx.x;
    int lt = blockIdx.y;
    int l0 = lt * 64;
    int b = bh >> 3, h = bh & 7;
    const __half* base = qkv + (long)b * Ln * 1536 + h * 64;
    __shared__ __align__(16) __half sId[2][64][64];
    __shared__ __align__(16) __half sTapT[2][64][68];   // pad 68: half2 stays 4B-aligned
    __shared__ __align__(4)  __half sLo[2][64], sHi[2][64];
    int t = threadIdx.x;
    #pragma unroll
    for (int sel = 0; sel < 2; sel++) {
        #pragma unroll
        for (int i = 0; i < 2; i++) {
            int idx = t + i * 256;
            int r  = idx >> 3;
            int c8 = (idx & 7) * 8;
            __half tmp[8];
            *(uint4*)tmp = *(const uint4*)&base[(long)(l0 + r) * 1536 + sel * 512 + c8];
            #pragma unroll
            for (int k = 0; k < 8; k++) tmp[k] = __float2half_rn(elu1f(__half2float(tmp[k])));
            *(uint4*)&sId[sel][r][c8] = *(uint4*)tmp;
            *(uint4*)tmp = *(const uint4*)&base[(long)(r * 32 + lt) * 1536 + sel * 512 + c8];
            #pragma unroll
            for (int k = 0; k < 8; k++)
                sTapT[sel][c8 + k][r] = __float2half_rn(elu1f(__half2float(tmp[k])));
        }
    }
    if (t < 128) {
        int sel = t >> 6, d = t & 63;
        float lo = 0.0f, hi = 0.0f;
        if (l0 > 0)       lo = elu1f(__half2float(base[(long)(d * 32 + lt - 1) * 1536 + sel * 512 + 63]));
        if (l0 + 64 < Ln) hi = elu1f(__half2float(base[(long)(d * 32 + lt + 1) * 1536 + sel * 512]));
        sLo[sel][d] = __float2half_rn(lo);
        sHi[sel][d] = __float2half_rn(hi);
    }
    __syncthreads();
    int d2 = (t & 31) * 2, rb = t >> 5;
    __half2 w0h = __floats2half2_rn(lw[d2*3],   lw[d2*3+3]);
    __half2 w1h = __floats2half2_rn(lw[d2*3+1], lw[d2*3+4]);
    __half2 w2h = __floats2half2_rn(lw[d2*3+2], lw[d2*3+5]);
    __half2 bi2 = __floats2half2_rn(lb[d2], lb[d2+1]);
    #pragma unroll
    for (int sel = 0; sel < 2; sel++) {
        __half* dst = sel ? k2 : q2;
        #pragma unroll
        for (int i = 0; i < 8; i++) {
            int r = rb + i * 8;
            __half2 c1 = *(__half2*)&sTapT[sel][r][d2];
            __half2 c0 = (r > 0)  ? *(__half2*)&sTapT[sel][r-1][d2] : *(__half2*)&sLo[sel][d2];
            __half2 c2 = (r < 63) ? *(__half2*)&sTapT[sel][r+1][d2] : *(__half2*)&sHi[sel][d2];
            __half2 o = __hadd2(*(__half2*)&sId[sel][r][d2], bi2);
            o = __hfma2(w0h, c0, o);
            o = __hfma2(w1h, c1, o);
            o = __hfma2(w2h, c2, o);
            *(__half2*)&dst[(long)bh * (Ln * Dn) + (long)(l0 + r) * 64 + d2] = o;
        }
    }
}

// ---------------- kv partials (half) + kmean partials (fused) ----------------
__global__ void kv_kernel(const __half* __restrict__ k2, const __half* __restrict__ qkv,
                          __half* __restrict__ part, float* __restrict__ kmpart) {
    int bh = blockIdx.x, chunk = blockIdx.y;
    int b = bh >> 3, h = bh & 7;
    __shared__ float ks[32][64];
    __shared__ float vs[32][64];
    int t = threadIdx.x;
    int e0 = (t & 15) * 4, d0 = (t >> 4) * 4;
    float acc[4][4] = {};
    float ksum[4] = {};
    bool kmwriter = (t & 15) == 0;
    int lc = Ln / KVCHUNKS;
    for (int l0 = chunk * lc; l0 < chunk * lc + lc; l0 += 32) {
        #pragma unroll
        for (int i = 0; i < 2; i++) {
            int idx = t + i * 256;
            int r = idx >> 4, c4 = (idx & 15) * 4;
            int l = l0 + r;
            uint2 kr = *(const uint2*)&k2[((long)bh * Ln + l) * 64 + c4];
            uint2 vr = *(const uint2*)&qkv[((long)(b * Ln + l)) * 1536 + 1024 + h * 64 + c4];
            float2 k0 = __half22float2(*(__half2*)&kr.x);
            float2 k1 = __half22float2(*(__half2*)&kr.y);
            float2 v0 = __half22float2(*(__half2*)&vr.x);
            float2 v1 = __half22float2(*(__half2*)&vr.y);
            ks[r][c4] = k0.x; ks[r][c4+1] = k0.y; ks[r][c4+2] = k1.x; ks[r][c4+3] = k1.y;
            vs[r][c4] = v0.x; vs[r][c4+1] = v0.y; vs[r][c4+2] = v1.x; vs[r][c4+3] = v1.y;
        }
        __syncthreads();
        #pragma unroll
        for (int l = 0; l < 32; l++) {
            float4 kr = *(const float4*)&ks[l][d0];
            float4 vr = *(const float4*)&vs[l][e0];
            float k_[4] = {kr.x, kr.y, kr.z, kr.w};
            float v_[4] = {vr.x, vr.y, vr.z, vr.w};
            if (kmwriter) {
                ksum[0] += k_[0]; ksum[1] += k_[1]; ksum[2] += k_[2]; ksum[3] += k_[3];
            }
            #pragma unroll
            for (int i = 0; i < 4; i++)
                #pragma unroll
                for (int j = 0; j < 4; j++)
                    acc[i][j] += k_[i] * v_[j];
        }
        __syncthreads();
    }
    __half* dst = part + ((long)chunk * BHn + bh) * (Dn * Dn);
    #pragma unroll
    for (int i = 0; i < 4; i++) {
        __half2 p0 = __floats2half2_rn(acc[i][0], acc[i][1]);
        __half2 p1 = __floats2half2_rn(acc[i][2], acc[i][3]);
        uint2 w; *(__half2*)&w.x = p0; *(__half2*)&w.y = p1;
        *(uint2*)&dst[(d0 + i) * 64 + e0] = w;
    }
    if (kmwriter) {
        float* kd = kmpart + ((long)chunk * BHn + bh) * Dn + d0;
        kd[0] = ksum[0]; kd[1] = ksum[1]; kd[2] = ksum[2]; kd[3] = ksum[3];
    }
}

// ---------------- reduce partials -> kvT2 (half, [bh][72][64]) ----------------
__global__ void kv_reduce_kernel(const __half* __restrict__ part, const float* __restrict__ kmpart,
                                 __half* __restrict__ kvT2) {
    int i = blockIdx.x * blockDim.x + threadIdx.x;
    if (i < BHn * 4096) {
        int bh = i >> 12;
        int de = i & 4095;
        int d = de >> 6, e = de & 63;
        float s = 0.0f;
        #pragma unroll
        for (int c = 0; c < KVCHUNKS; c++) s += __half2float(part[(long)c * (BHn * 4096) + i]);
        kvT2[(long)bh * 4608 + e * 64 + d] = __float2half_rn(s * (1.0f / Ln));
    } else if (i < BHn * 4096 + BHn * 64) {
        int j = i - BHn * 4096;
        int bh = j >> 6, d = j & 63;
        float s = 0.0f;
        #pragma unroll
        for (int c = 0; c < KVCHUNKS; c++) s += kmpart[(long)c * (BHn * 64) + j];
        kvT2[(long)bh * 4608 + 4096 + d] = __float2half_rn(s * (1.0f / Ln));
    } else if (i < BHn * 4096 + BHn * 64 + BHn * 448) {
        int j = i - BHn * 4096 - BHn * 64;
        int bh = j / 448, rr = j % 448;
        kvT2[(long)bh * 4608 + 4160 + rr] = __ushort_as_half((unsigned short)0);
    }
}

// ---------------- attention output via mma: xbufh = x + (q2@kvT^T) * z ----------------
__global__ void attn_out_kernel(const __half* __restrict__ q2, const __half* __restrict__ kvT2,
                                const float* __restrict__ x, __half* __restrict__ xbuf) {
    int bh = blockIdx.x, b = bh >> 3, h = bh & 7;
    int lbase = blockIdx.y * 128;
    __shared__ __align__(16) __half qs[128 * 64];
    __shared__ __align__(16) __half bs[72 * 64];
    int t = threadIdx.x, wid = t >> 5, lane = t & 31;
    int g = lane >> 2, tig = lane & 3;
    #pragma unroll
    for (int i = 0; i < 4; i++) {
        int idx = t + i * 256;
        int r = idx >> 3, c = idx & 7;
        *(uint4*)((char*)qs + r * 128 + ((c ^ (r & 7)) << 4)) =
            *(const uint4*)&q2[((long)bh * Ln + lbase + r) * 64 + c * 8];
    }
    #pragma unroll
    for (int i = 0; i < 3; i++) {
        int idx = t + i * 256;
        if (idx < 576) {
            int r = idx >> 3, c = idx & 7;
            *(uint4*)((char*)bs + r * 128 + ((c ^ (r & 7)) << 4)) =
                *(const uint4*)&kvT2[(long)bh * 4608 + r * 64 + c * 8];
        }
    }
    __syncthreads();
    uint32_t sq = smem_u32(qs), sbm = smem_u32(bs);
    uint32_t m = (uint32_t)(wid * 16 + (lane & 15));
    uint32_t aRow = m * 128, aSw = m & 7, cHiA = (uint32_t)(lane >> 4);
    float acc[9][4] = {};
    #pragma unroll
    for (int kb = 0; kb < 4; kb++) {
        uint32_t a[4];
        ldsm4(a, sq + aRow + ((((uint32_t)(2 * kb) | cHiA) ^ aSw) << 4));
        #pragma unroll
        for (int np = 0; np < 4; np++) {
            uint32_t r = (uint32_t)(np * 16 + ((lane >> 4) << 3) + (lane & 7));
            uint32_t ch = (uint32_t)(2 * kb) | (uint32_t)((lane >> 3) & 1);
            uint32_t bb[4];
            ldsm4(bb, sbm + r * 128 + ((ch ^ (r & 7)) << 4));
            uint32_t b0[2] = {bb[0], bb[1]}, b1[2] = {bb[2], bb[3]};
            mma_f16(acc[2 * np],     a, b0);
            mma_f16(acc[2 * np + 1], a, b1);
        }
        {
            uint32_t r = (uint32_t)(64 + (lane & 7));
            uint32_t ch = (uint32_t)(2 * kb) | (uint32_t)((lane >> 3) & 1);
            uint32_t bb[2];
            ldsm2(bb, sbm + r * 128 + ((ch ^ (r & 7)) << 4));
            mma_f16(acc[8], a, bb);
        }
    }
    float zg  = __shfl_sync(0xFFFFFFFFu, acc[8][0], lane & ~3) + 1e-6f;
    float zg8 = __shfl_sync(0xFFFFFFFFu, acc[8][2], lane & ~3) + 1e-6f;
    zg = 1.0f / zg;
    zg8 = 1.0f / zg8;
    int row0 = lbase + wid * 16 + g;
    #pragma unroll
    for (int nt = 0; nt < 8; nt++) {
        int col = h * 64 + nt * 8 + tig * 2;
        long off0 = (long)(b * Ln + row0) * Cn + col;
        long off1 = off0 + 8L * Cn;
        float2 x0 = *(const float2*)&x[off0];
        float2 x1 = *(const float2*)&x[off1];
        *(__half2*)&xbuf[off0] = __floats2half2_rn(x0.x + acc[nt][0] * zg,  x0.y + acc[nt][1] * zg);
        *(__half2*)&xbuf[off1] = __floats2half2_rn(x1.x + acc[nt][2] * zg8, x1.y + acc[nt][3] * zg8);
    }
}

// ================= fp16 mma.sync GEMM, K-chunk 64, 3-stage =================
#define GSTG 32768
#define GSM  (3 * GSTG)

template<int EPI, int CONVA>
__global__ void __launch_bounds__(256, 2)
gemm_h(const __half* __restrict__ A, const __half* __restrict__ Bt,
       const float* __restrict__ bias, const void* __restrict__ resv,
       void* __restrict__ Cv, int M, int N, int K) {
    extern __shared__ char smraw[];
    uint32_t sb = smem_u32(smraw);
    int t = threadIdx.x, wid = t >> 5, lane = t & 31;
    int g = lane >> 2, tig = lane & 3;
    int bm = blockIdx.y * 128, bn = blockIdx.x * 128;
    int wm = (wid >> 2) * 64, wn = (wid & 3) * 32;

    const __half* aG[4]; const __half* bG[4]; uint32_t offA[4], offB[4];
    int rs[4], cs[4];
    #pragma unroll
    for (int i = 0; i < 4; i++) {
        int idx = t + i * 256;
        int r = idx >> 3;
        int c = idx & 7;
        rs[i] = r; cs[i] = c;
        uint32_t off = (uint32_t)r * 128 + (uint32_t)((c ^ (r & 7)) << 4);
        offA[i] = off;
        offB[i] = off + 16384;
        if (!CONVA) aG[i] = A + (long)(bm + r) * K + c * 8;
        bG[i] = Bt + (long)(bn + r) * K + c * 8;
    }

    uint32_t aRow[4], aSw[4];
    #pragma unroll
    for (int mt = 0; mt < 4; mt++) {
        uint32_t m = wm + mt * 16 + (lane & 15);
        aRow[mt] = m * 128;
        aSw[mt] = m & 7;
    }
    uint32_t cHiA = lane >> 4;
    uint32_t bRow[2], bSw[2];
    #pragma unroll
    for (int np = 0; np < 2; np++) {
        uint32_t n = wn + np * 16 + ((lane >> 4) << 3) + (lane & 7);
        bRow[np] = n * 128 + 16384;
        bSw[np] = n & 7;
    }
    uint32_t cHiB = (lane >> 3) & 1;

    int nk = K >> 6;

    auto loadA_conv = [&](uint32_t stb, int kt) {
        int tap = kt >> 3;
        int kin = (kt & 7) * 64;
        #pragma unroll
        for (int i = 0; i < 4; i++) {
            long row = bm + rs[i];
            int l = (int)(row & (Ln - 1));
            bool valid = (unsigned)(l + tap - 1) < (unsigned)Ln;
            const __half* src = valid ? (A + (row + tap - 1) * Cn + kin + cs[i] * 8) : A;
            cpasync16z(stb + offA[i], src, valid ? 16u : 0u);
        }
    };

    #pragma unroll
    for (int s = 0; s < 2; s++) {
        uint32_t stb = sb + s * GSTG;
        if (CONVA) loadA_conv(stb, s);
        else {
            #pragma unroll
            for (int i = 0; i < 4; i++) cpasync16(stb + offA[i], aG[i] + s * 64);
        }
        #pragma unroll
        for (int i = 0; i < 4; i++) cpasync16(stb + offB[i], bG[i] + s * 64);
        CP_COMMIT();
    }
    CP_WAIT1();
    __syncthreads();

    float acc[4][4][4] = {};

    for (int kt = 0; kt < nk; kt++) {
        if (kt + 2 < nk) {
            uint32_t stb = sb + ((kt + 2) % 3) * GSTG;
            if (CONVA) loadA_conv(stb, kt + 2);
            else {
                #pragma unroll
                for (int i = 0; i < 4; i++) cpasync16(stb + offA[i], aG[i] + (long)(kt + 2) * 64);
            }
            #pragma unroll
            for (int i = 0; i < 4; i++) cpasync16(stb + offB[i], bG[i] + (long)(kt + 2) * 64);
        }
        CP_COMMIT();

        uint32_t stb = sb + (kt % 3) * GSTG;
        #pragma unroll
        for (int kb = 0; kb < 4; kb++) {
            uint32_t a[4][4], b[4][2];
            #pragma unroll
            for (int mt = 0; mt < 4; mt++) {
                uint32_t addr = stb + aRow[mt] + ((((uint32_t)(2 * kb) | cHiA) ^ aSw[mt]) << 4);
                ldsm4(a[mt], addr);
            }
            #pragma unroll
            for (int np = 0; np < 2; np++) {
                uint32_t bb[4];
                uint32_t addr = stb + bRow[np] + ((((uint32_t)(2 * kb) | cHiB) ^ bSw[np]) << 4);
                ldsm4(bb, addr);
                b[2*np][0] = bb[0]; b[2*np][1] = bb[1];
                b[2*np+1][0] = bb[2]; b[2*np+1][1] = bb[3];
            }
            #pragma unroll
            for (int mt = 0; mt < 4; mt++)
                #pragma unroll
                for (int nt = 0; nt < 4; nt++)
                    mma_f16(acc[mt][nt], a[mt], b[nt]);
        }

        CP_WAIT1();
        __syncthreads();
    }

    // ---- epilogue ----
    if (EPI == 3) {
        float* sg = (float*)smraw;
        #pragma unroll
        for (int mt = 0; mt < 4; mt++) {
            int r0 = wm + mt * 16 + g;
            #pragma unroll
            for (int nt = 0; nt < 4; nt++) {
                int col = wn + nt * 8 + tig * 2;
                float b0 = bias[bn + col], b1 = bias[bn + col + 1];
                float vv0 = acc[mt][nt][0] + b0, gg0 = acc[mt][nt][1] + b1;
                float vv1 = acc[mt][nt][2] + b0, gg1 = acc[mt][nt][3] + b1;
                int cp = col >> 1;
                sg[r0 * 68 + cp]       = vv0 / (1.0f + __expf(-gg0));
                sg[(r0 + 8) * 68 + cp] = vv1 / (1.0f + __expf(-gg1));
            }
        }
        __syncthreads();
        int cpb = bn >> 1;
        __half* X = (__half*)Cv;
        const __half* R = (const __half*)resv;
        #pragma unroll
        for (int i = 0; i < 8; i++) {
            int j = t + i * 256;
            int r = j >> 4, c4 = j & 15;
            long off = (long)(bm + r) * Cn + cpb + c4 * 4;
            uint2 xraw = *(uint2*)(X + off);
            uint2 spraw = *(const uint2*)(R + off);
            float2 x0 = __half22float2(*(__half2*)&xraw.x);
            float2 x1 = __half22float2(*(__half2*)&xraw.y);
            float2 s0 = __half22float2(*(__half2*)&spraw.x);
            float2 s1 = __half22float2(*(__half2*)&spraw.y);
            float4 gv = *(float4*)&sg[r * 68 + c4 * 4];
            uint2 outp;
            *(__half2*)&outp.x = __floats2half2_rn(x0.x + s0.x + gv.x, x0.y + s0.y + gv.y);
            *(__half2*)&outp.y = __floats2half2_rn(x1.x + s1.x + gv.z, x1.y + s1.y + gv.w);
            *(uint2*)(X + off) = outp;
        }
        return;
    }

    #pragma unroll
    for (int mt = 0; mt < 4; mt++) {
        int row = bm + wm + mt * 16 + g;
        #pragma unroll
        for (int nt = 0; nt < 4; nt++) {
            int col = bn + wn + nt * 8 + tig * 2;
            float b0 = bias[col], b1 = bias[col + 1];
            float v00 = acc[mt][nt][0] + b0;
            float v01 = acc[mt][nt][1] + b1;
            float v10 = acc[mt][nt][2] + b0;
            float v11 = acc[mt][nt][3] + b1;
            if (EPI == 1) {
                v00 = 0.5f * v00 * (1.0f + erff(v00 * 0.70710678118654752f));
                v01 = 0.5f * v01 * (1.0f + erff(v01 * 0.70710678118654752f));
                v10 = 0.5f * v10 * (1.0f + erff(v10 * 0.70710678118654752f));
                v11 = 0.5f * v11 * (1.0f + erff(v11 * 0.70710678118654752f));
                __half2* C = (__half2*)Cv;
                C[((long)row * N + col) >> 1]       = __floats2half2_rn(v00, v01);
                C[((long)(row + 8) * N + col) >> 1] = __floats2half2_rn(v10, v11);
            } else if (EPI == 4) {
                __half2* C = (__half2*)Cv;
                C[((long)row * N + col) >> 1]       = __floats2half2_rn(v00, v01);
                C[((long)(row + 8) * N + col) >> 1] = __floats2half2_rn(v10, v11);
            } else {  // EPI == 2
                const __half2* R = (const __half2*)resv;
                float2 f0 = __half22float2(R[((long)row * N + col) >> 1]);
                float2 f1 = __half22float2(R[((long)(row + 8) * N + col) >> 1]);
                v00 += f0.x; v01 += f0.y;
                v10 += f1.x; v11 += f1.y;
                float* C = (float*)Cv;
                float2 p0 = {v00, v01}, p1 = {v10, v11};
                *(float2*)(C + (long)row * N + col)       = p0;
                *(float2*)(C + (long)(row + 8) * N + col) = p1;
            }
        }
    }
}

// ---------------- host launcher ----------------
extern "C" void kernel_launch(void* const* d_in, const int* in_sizes, int n_in,
                              void* d_out, int out_size) {
    const float* x      = (const float*)d_in[0];
    const float* g1     = (const float*)d_in[1];
    const float* b1     = (const float*)d_in[2];
    const float* qk_w   = (const float*)d_in[3];
    const float* qk_b   = (const float*)d_in[4];
    const float* v_w    = (const float*)d_in[5];
    const float* v_b    = (const float*)d_in[6];
    const float* lepe_w = (const float*)d_in[7];
    const float* lepe_b = (const float*)d_in[8];
    const float* g2     = (const float*)d_in[9];
    const float* b2     = (const float*)d_in[10];
    const float* spn_g  = (const float*)d_in[11];
    const float* spn_b  = (const float*)d_in[12];
    const float* sp_cw  = (const float*)d_in[13];
    const float* sp_cb  = (const float*)d_in[14];
    const float* g3     = (const float*)d_in[15];
    const float* b3     = (const float*)d_in[16];
    const float* w1     = (const float*)d_in[17];
    const float* bb1    = (const float*)d_in[18];
    const float* w2     = (const float*)d_in[19];
    const float* bb2    = (const float*)d_in[20];
    float* out = (float*)d_out;

    float *kmpart, *bias2, *bias3;
    __half *xbufh, *lnh, *qkvh, *q2h, *k2h, *kvpart, *kvT2h, *spinh, *hb, *ffnh;
    __half *qkvTh, *w1Th, *w2Th, *wtT2h;
    cudaGetSymbolAddress((void**)&xbufh,  g_xbufh);
    cudaGetSymbolAddress((void**)&lnh,    g_lnh);
    cudaGetSymbolAddress((void**)&qkvh,   g_qkvh);
    cudaGetSymbolAddress((void**)&q2h,    g_q2h);
    cudaGetSymbolAddress((void**)&k2h,    g_k2h);
    cudaGetSymbolAddress((void**)&kvpart, g_kvpart);
    cudaGetSymbolAddress((void**)&kmpart, g_kmpart);
    cudaGetSymbolAddress((void**)&kvT2h,  g_kvT2h);
    cudaGetSymbolAddress((void**)&spinh,  g_spinh);
    cudaGetSymbolAddress((void**)&hb,     g_hb);
    cudaGetSymbolAddress((void**)&ffnh,   g_ffnh);
    cudaGetSymbolAddress((void**)&qkvTh,  g_qkvTh);
    cudaGetSymbolAddress((void**)&w1Th,   g_w1Th);
    cudaGetSymbolAddress((void**)&w2Th,   g_w2Th);
    cudaGetSymbolAddress((void**)&wtT2h,  g_wtT2h);
    cudaGetSymbolAddress((void**)&bias2,  g_bias2);
    cudaGetSymbolAddress((void**)&bias3,  g_bias3);

    cudaFuncSetAttribute((const void*)gemm_h<4,0>, cudaFuncAttributeMaxDynamicSharedMemorySize, GSM);
    cudaFuncSetAttribute((const void*)gemm_h<3,1>, cudaFuncAttributeMaxDynamicSharedMemorySize, GSM);
    cudaFuncSetAttribute((const void*)gemm_h<1,0>, cudaFuncAttributeMaxDynamicSharedMemorySize, GSM);
    cudaFuncSetAttribute((const void*)gemm_h<2,0>, cudaFuncAttributeMaxDynamicSharedMemorySize, GSM);

    prep_weights_kernel<<<(int)((PW_TOT + 255) / 256), 256>>>(
        qk_w, v_w, w1, w2, sp_cw, qk_b, v_b, sp_cb,
        qkvTh, w1Th, w2Th, wtT2h, bias2, bias3);

    // Block 1: xbufh = x + attn(LN1(x))
    ln_h_kernel<<<BLn, 128>>>(x, g1, b1, lnh);
    gemm_h<4,0><<<dim3(1536 / 128, BLn / 128), 256, GSM>>>(lnh, qkvTh, bias3, nullptr, qkvh, BLn, 1536, Cn);
    qk_post_kernel<<<dim3(BHn, Ln / 64), 256>>>(qkvh, lepe_w, lepe_b, q2h, k2h);
    kv_kernel<<<dim3(BHn, KVCHUNKS), 256>>>(k2h, qkvh, kvpart, kmpart);
    kv_reduce_kernel<<<(BHn * 4096 + BHn * 64 + BHn * 448 + 255) / 256, 256>>>(kvpart, kmpart, kvT2h);
    attn_out_kernel<<<dim3(BHn, Ln / 128), 256>>>(q2h, kvT2h, x, xbufh);

    // Block 2: gated conv state path
    ln2ln3_kernel<<<BLn, 128>>>(xbufh, g2, b2, spn_g, spn_b, spinh, hb);
    gemm_h<3,1><<<dim3(1024 / 128, BLn / 128), 256, GSM>>>(hb, wtT2h, bias2, spinh, xbufh, BLn, 1024, 3 * Cn);

    // Block 3: FFN
    ln_hh_kernel<<<BLn, 128>>>(xbufh, g3, b3, lnh);
    gemm_h<1,0><<<dim3(FFn / 128, BLn / 128), 256, GSM>>>(lnh, w1Th, bb1, nullptr, ffnh, BLn, FFn, Cn);
    gemm_h<2,0><<<dim3(512 / 128, BLn / 128), 256, GSM>>>(ffnh, w2Th, bb2, xbufh, out, BLn, 512, FFn);
}

// round 17
// speedup vs baseline: 1.5371x; 1.5371x over previous
#include <cuda_runtime.h>
#include <cuda_fp16.h>
#include <math.h>
#include <stdint.h>

#define Bn 8
#define Ln 2048
#define Cn 512
#define Hn 8
#define Dn 64
#define FFn 2048
#define BLn (Bn*Ln)          /* 16384 */
#define BHn (Bn*Hn)          /* 64    */
#define BHLn (BHn*Ln)        /* 131072*/
#define KVCHUNKS 8

// ---------------- scratch (static device globals; no allocation) ----------------
static __device__ __align__(16) __half g_xbufh[BLn*Cn];
static __device__ __align__(16) __half g_lnh[BLn*Cn];
static __device__ __align__(16) __half g_qkvh[(long)BLn*1536];
static __device__ __align__(16) __half g_q2h[BHLn*Dn];
static __device__ __align__(16) __half g_k2h[BHLn*Dn];
static __device__ __align__(16) __half g_kvpart[KVCHUNKS*BHn*Dn*Dn];
static __device__ __align__(16) float  g_kmpart[KVCHUNKS*BHn*Dn];
static __device__ __align__(16) __half g_kvT2h[BHn*72*64];   // B^T tiles + km row + zero pad
static __device__ __align__(16) __half g_spinh[BLn*Cn];
static __device__ __align__(16) __half g_hb[BLn*Cn];
static __device__ __align__(16) __half g_ffnh[(long)BLn*FFn];
// weights (half), prepared once per call
static __device__ __align__(16) __half g_qkvTh[1536*512];
static __device__ __align__(16) __half g_w1Th[2048*512];
static __device__ __align__(16) __half g_w2Th[512*2048];
static __device__ __align__(16) __half g_wtT2h[1024*1536];
static __device__ __align__(16) float  g_bias2[1024];
static __device__ __align__(16) float  g_bias3[1536];

// ---------------- PTX helpers ----------------
__device__ __forceinline__ uint32_t smem_u32(const void* p) {
    uint32_t a;
    asm("{ .reg .u64 t; cvta.to.shared.u64 t, %1; cvt.u32.u64 %0, t; }" : "=r"(a) : "l"(p));
    return a;
}
__device__ __forceinline__ void cpasync16(uint32_t saddr, const void* g) {
    asm volatile("cp.async.cg.shared.global [%0], [%1], 16;" :: "r"(saddr), "l"(g) : "memory");
}
__device__ __forceinline__ void cpasync16z(uint32_t saddr, const void* g, uint32_t sz) {
    asm volatile("cp.async.cg.shared.global [%0], [%1], 16, %2;"
                 :: "r"(saddr), "l"(g), "r"(sz) : "memory");
}
#define CP_COMMIT() asm volatile("cp.async.commit_group;" ::: "memory")
#define CP_WAIT1()  asm volatile("cp.async.wait_group 1;" ::: "memory")

__device__ __forceinline__ void ldsm4(uint32_t* r, uint32_t addr) {
    asm volatile("ldmatrix.sync.aligned.m8n8.x4.shared.b16 {%0,%1,%2,%3}, [%4];"
        : "=r"(r[0]), "=r"(r[1]), "=r"(r[2]), "=r"(r[3]) : "r"(addr));
}
__device__ __forceinline__ void ldsm2(uint32_t* r, uint32_t addr) {
    asm volatile("ldmatrix.sync.aligned.m8n8.x2.shared.b16 {%0,%1}, [%2];"
        : "=r"(r[0]), "=r"(r[1]) : "r"(addr));
}
__device__ __forceinline__ void mma_f16(float* c, const uint32_t* a, const uint32_t* b) {
    asm volatile(
        "mma.sync.aligned.m16n8k16.row.col.f32.f16.f16.f32 "
        "{%0,%1,%2,%3}, {%4,%5,%6,%7}, {%8,%9}, {%0,%1,%2,%3};"
        : "+f"(c[0]), "+f"(c[1]), "+f"(c[2]), "+f"(c[3])
        : "r"(a[0]), "r"(a[1]), "r"(a[2]), "r"(a[3]), "r"(b[0]), "r"(b[1]));
}

// ---------------- small helpers ----------------
__device__ __forceinline__ float elu1f(float x) { return x > 0.0f ? x + 1.0f : __expf(x); }

// ---------------- one-shot weight prep ----------------
#define PW_S0 524288L
#define PW_S1 (PW_S0 + 262144L)
#define PW_S2 (PW_S1 + 1048576L)
#define PW_S3 (PW_S2 + 1048576L)
#define PW_S4 (PW_S3 + 1572864L)
#define PW_TOT (PW_S4 + 1536L)
__global__ void prep_weights_kernel(const float* __restrict__ qk_w, const float* __restrict__ v_w,
                                    const float* __restrict__ w1, const float* __restrict__ w2,
                                    const float* __restrict__ sp_cw,
                                    const float* __restrict__ qk_b, const float* __restrict__ v_b,
                                    const float* __restrict__ sp_cb,
                                    __half* __restrict__ qkvT, __half* __restrict__ w1T,
                                    __half* __restrict__ w2T, __half* __restrict__ wtT2,
                                    float* __restrict__ bias2, float* __restrict__ bias3) {
    long idx = (long)blockIdx.x * blockDim.x + threadIdx.x;
    if (idx < PW_S0) {
        int k = (int)(idx & 511), n = (int)(idx >> 9);
        qkvT[idx] = __float2half_rn(qk_w[(long)k * 1024 + n]);
    } else if (idx < PW_S1) {
        long i = idx - PW_S0;
        int k = (int)(i & 511), n = (int)(i >> 9);
        qkvT[idx] = __float2half_rn(v_w[(long)k * 512 + n]);
    } else if (idx < PW_S2) {
        long i = idx - PW_S1;
        int k = (int)(i & 511), n = (int)(i >> 9);
        w1T[i] = __float2half_rn(w1[(long)k * 2048 + n]);
    } else if (idx < PW_S3) {
        long i = idx - PW_S2;
        int k = (int)(i & 2047), n = (int)(i >> 11);
        w2T[i] = __float2half_rn(w2[(long)k * 512 + n]);
    } else if (idx < PW_S4) {
        long i = idx - PW_S3;
        int kk = (int)(i % 1536), n2 = (int)(i / 1536);
        int co = (n2 & 1) * 512 + (n2 >> 1);
        int k  = kk >> 9, ci = kk & 511;
        wtT2[i] = __float2half_rn(sp_cw[co * 1536 + ci * 3 + k]);
        if (kk == 0) bias2[n2] = sp_cb[co];
    } else if (idx < PW_TOT) {
        int j = (int)(idx - PW_S4);
        bias3[j] = (j < 1024) ? qk_b[j] : v_b[j - 1024];
    }
}

// ---------------- LayerNorm, float input -> half out ----------------
__global__ void ln_h_kernel(const float* __restrict__ in, const float* __restrict__ gam,
                            const float* __restrict__ bet, __half* __restrict__ out) {
    int row = blockIdx.x;
    int t = threadIdx.x;
    const float4 v = ((const float4*)(in + (long)row * Cn))[t];
    float s  = v.x + v.y + v.z + v.w;
    float sq = v.x*v.x + v.y*v.y + v.z*v.z + v.w*v.w;
    #pragma unroll
    for (int o = 16; o; o >>= 1) {
        s  += __shfl_xor_sync(0xFFFFFFFFu, s,  o);
        sq += __shfl_xor_sync(0xFFFFFFFFu, sq, o);
    }
    __shared__ float ss[4], ssq[4];
    if ((t & 31) == 0) { ss[t >> 5] = s; ssq[t >> 5] = sq; }
    __syncthreads();
    s  = ss[0] + ss[1] + ss[2] + ss[3];
    sq = ssq[0] + ssq[1] + ssq[2] + ssq[3];
    float mu   = s * (1.0f / Cn);
    float var  = sq * (1.0f / Cn) - mu * mu;
    float rstd = rsqrtf(var + 1e-5f);
    float4 g4 = ((const float4*)gam)[t];
    float4 b4 = ((const float4*)bet)[t];
    __half2* o = (__half2*)(out + (long)row * Cn);
    o[t * 2]     = __floats2half2_rn((v.x - mu) * rstd * g4.x + b4.x,
                                     (v.y - mu) * rstd * g4.y + b4.y);
    o[t * 2 + 1] = __floats2half2_rn((v.z - mu) * rstd * g4.z + b4.z,
                                     (v.w - mu) * rstd * g4.w + b4.w);
}

// ---------------- LayerNorm, half input -> half out ----------------
__global__ void ln_hh_kernel(const __half* __restrict__ in, const float* __restrict__ gam,
                             const float* __restrict__ bet, __half* __restrict__ out) {
    int row = blockIdx.x;
    int t = threadIdx.x;
    uint2 raw = ((const uint2*)(in + (long)row * Cn))[t];
    float2 p0 = __half22float2(*(__half2*)&raw.x);
    float2 p1 = __half22float2(*(__half2*)&raw.y);
    float4 v = {p0.x, p0.y, p1.x, p1.y};
    float s  = v.x + v.y + v.z + v.w;
    float sq = v.x*v.x + v.y*v.y + v.z*v.z + v.w*v.w;
    #pragma unroll
    for (int o = 16; o; o >>= 1) {
        s  += __shfl_xor_sync(0xFFFFFFFFu, s,  o);
        sq += __shfl_xor_sync(0xFFFFFFFFu, sq, o);
    }
    __shared__ float ss[4], ssq[4];
    if ((t & 31) == 0) { ss[t >> 5] = s; ssq[t >> 5] = sq; }
    __syncthreads();
    s  = ss[0] + ss[1] + ss[2] + ss[3];
    sq = ssq[0] + ssq[1] + ssq[2] + ssq[3];
    float mu   = s * (1.0f / Cn);
    float var  = sq * (1.0f / Cn) - mu * mu;
    float rstd = rsqrtf(var + 1e-5f);
    float4 g4 = ((const float4*)gam)[t];
    float4 b4 = ((const float4*)bet)[t];
    __half2* o = (__half2*)(out + (long)row * Cn);
    o[t * 2]     = __floats2half2_rn((v.x - mu) * rstd * g4.x + b4.x,
                                     (v.y - mu) * rstd * g4.y + b4.y);
    o[t * 2 + 1] = __floats2half2_rn((v.z - mu) * rstd * g4.z + b4.z,
                                     (v.w - mu) * rstd * g4.w + b4.w);
}

// ---------------- fused LN2 + LN3 (half in) ----------------
__global__ void ln2ln3_kernel(const __half* __restrict__ in,
                              const float* __restrict__ g2, const float* __restrict__ b2,
                              const float* __restrict__ g3, const float* __restrict__ b3,
                              __half* __restrict__ spin, __half* __restrict__ hb) {
    int row = blockIdx.x;
    int t = threadIdx.x;
    __shared__ float ss[4], ssq[4];
    uint2 raw = ((const uint2*)(in + (long)row * Cn))[t];
    float2 p0 = __half22float2(*(__half2*)&raw.x);
    float2 p1 = __half22float2(*(__half2*)&raw.y);
    float4 v = {p0.x, p0.y, p1.x, p1.y};
    float s  = v.x + v.y + v.z + v.w;
    float sq = v.x*v.x + v.y*v.y + v.z*v.z + v.w*v.w;
    #pragma unroll
    for (int o = 16; o; o >>= 1) {
        s  += __shfl_xor_sync(0xFFFFFFFFu, s,  o);
        sq += __shfl_xor_sync(0xFFFFFFFFu, sq, o);
    }
    if ((t & 31) == 0) { ss[t >> 5] = s; ssq[t >> 5] = sq; }
    __syncthreads();
    s  = ss[0] + ss[1] + ss[2] + ss[3];
    sq = ssq[0] + ssq[1] + ssq[2] + ssq[3];
    float mu   = s * (1.0f / Cn);
    float var  = sq * (1.0f / Cn) - mu * mu;
    float rstd = rsqrtf(var + 1e-5f);
    float4 gg = ((const float4*)g2)[t];
    float4 bb = ((const float4*)b2)[t];
    float4 o1;
    o1.x = (v.x - mu) * rstd * gg.x + bb.x;
    o1.y = (v.y - mu) * rstd * gg.y + bb.y;
    o1.z = (v.z - mu) * rstd * gg.z + bb.z;
    o1.w = (v.w - mu) * rstd * gg.w + bb.w;
    __half2* sp = (__half2*)(spin + (long)row * Cn);
    sp[t * 2]     = __floats2half2_rn(o1.x, o1.y);
    sp[t * 2 + 1] = __floats2half2_rn(o1.z, o1.w);
    float s2  = o1.x + o1.y + o1.z + o1.w;
    float sq2 = o1.x*o1.x + o1.y*o1.y + o1.z*o1.z + o1.w*o1.w;
    #pragma unroll
    for (int o = 16; o; o >>= 1) {
        s2  += __shfl_xor_sync(0xFFFFFFFFu, s2,  o);
        sq2 += __shfl_xor_sync(0xFFFFFFFFu, sq2, o);
    }
    __syncthreads();
    if ((t & 31) == 0) { ss[t >> 5] = s2; ssq[t >> 5] = sq2; }
    __syncthreads();
    s2  = ss[0] + ss[1] + ss[2] + ss[3];
    sq2 = ssq[0] + ssq[1] + ssq[2] + ssq[3];
    float mu2   = s2 * (1.0f / Cn);
    float var2  = sq2 * (1.0f / Cn) - mu2 * mu2;
    float rstd2 = rsqrtf(var2 + 1e-5f);
    float4 g4 = ((const float4*)g3)[t];
    float4 b4 = ((const float4*)b3)[t];
    __half2* o = (__half2*)(hb + (long)row * Cn);
    o[t * 2]     = __floats2half2_rn((o1.x - mu2) * rstd2 * g4.x + b4.x,
                                     (o1.y - mu2) * rstd2 * g4.y + b4.y);
    o[t * 2 + 1] = __floats2half2_rn((o1.z - mu2) * rstd2 * g4.z + b4.z,
                                     (o1.w - mu2) * rstd2 * g4.w + b4.w);
}

// ---------------- qk post: elu at smem fill, half2 FMA LePE ----------------
__global__ void qk_post_kernel(const __half* __restrict__ qkv,
                               const float* __restrict__ lw, const float* __restrict__ lb,
                               __half* __restrict__ q2, __half* __restrict__ k2) {
    int bh = blockIdx.x;
    int lt = blockIdx.y;
    int l0 = lt * 64;
    int b = bh >> 3, h = bh & 7;
    const __half* base = qkv + (long)b * Ln * 1536 + h * 64;
    __shared__ __align__(16) __half sId[2][64][64];
    __shared__ __align__(16) __half sTapT[2][64][68];   // pad 68: half2 stays 4B-aligned
    __shared__ __align__(4)  __half sLo[2][64], sHi[2][64];
    int t = threadIdx.x;
    #pragma unroll
    for (int sel = 0; sel < 2; sel++) {
        #pragma unroll
        for (int i = 0; i < 2; i++) {
            int idx = t + i * 256;
            int r  = idx >> 3;
            int c8 = (idx & 7) * 8;
            __half tmp[8];
            *(uint4*)tmp = *(const uint4*)&base[(long)(l0 + r) * 1536 + sel * 512 + c8];
            #pragma unroll
            for (int k = 0; k < 8; k++) tmp[k] = __float2half_rn(elu1f(__half2float(tmp[k])));
            *(uint4*)&sId[sel][r][c8] = *(uint4*)tmp;
            *(uint4*)tmp = *(const uint4*)&base[(long)(r * 32 + lt) * 1536 + sel * 512 + c8];
            #pragma unroll
            for (int k = 0; k < 8; k++)
                sTapT[sel][c8 + k][r] = __float2half_rn(elu1f(__half2float(tmp[k])));
        }
    }
    if (t < 128) {
        int sel = t >> 6, d = t & 63;
        float lo = 0.0f, hi = 0.0f;
        if (l0 > 0)       lo = elu1f(__half2float(base[(long)(d * 32 + lt - 1) * 1536 + sel * 512 + 63]));
        if (l0 + 64 < Ln) hi = elu1f(__half2float(base[(long)(d * 32 + lt + 1) * 1536 + sel * 512]));
        sLo[sel][d] = __float2half_rn(lo);
        sHi[sel][d] = __float2half_rn(hi);
    }
    __syncthreads();
    int d2 = (t & 31) * 2, rb = t >> 5;
    __half2 w0h = __floats2half2_rn(lw[d2*3],   lw[d2*3+3]);
    __half2 w1h = __floats2half2_rn(lw[d2*3+1], lw[d2*3+4]);
    __half2 w2h = __floats2half2_rn(lw[d2*3+2], lw[d2*3+5]);
    __half2 bi2 = __floats2half2_rn(lb[d2], lb[d2+1]);
    #pragma unroll
    for (int sel = 0; sel < 2; sel++) {
        __half* dst = sel ? k2 : q2;
        #pragma unroll
        for (int i = 0; i < 8; i++) {
            int r = rb + i * 8;
            __half2 c1 = *(__half2*)&sTapT[sel][r][d2];
            __half2 c0 = (r > 0)  ? *(__half2*)&sTapT[sel][r-1][d2] : *(__half2*)&sLo[sel][d2];
            __half2 c2 = (r < 63) ? *(__half2*)&sTapT[sel][r+1][d2] : *(__half2*)&sHi[sel][d2];
            __half2 o = __hadd2(*(__half2*)&sId[sel][r][d2], bi2);
            o = __hfma2(w0h, c0, o);
            o = __hfma2(w1h, c1, o);
            o = __hfma2(w2h, c2, o);
            *(__half2*)&dst[(long)bh * (Ln * Dn) + (long)(l0 + r) * 64 + d2] = o;
        }
    }
}

// ---------------- kv partials (half) + kmean partials (fused) ----------------
__global__ void kv_kernel(const __half* __restrict__ k2, const __half* __restrict__ qkv,
                          __half* __restrict__ part, float* __restrict__ kmpart) {
    int bh = blockIdx.x, chunk = blockIdx.y;
    int b = bh >> 3, h = bh & 7;
    __shared__ float ks[32][64];
    __shared__ float vs[32][64];
    int t = threadIdx.x;
    int e0 = (t & 15) * 4, d0 = (t >> 4) * 4;
    float acc[4][4] = {};
    float ksum[4] = {};
    bool kmwriter = (t & 15) == 0;
    int lc = Ln / KVCHUNKS;
    for (int l0 = chunk * lc; l0 < chunk * lc + lc; l0 += 32) {
        #pragma unroll
        for (int i = 0; i < 2; i++) {
            int idx = t + i * 256;
            int r = idx >> 4, c4 = (idx & 15) * 4;
            int l = l0 + r;
            uint2 kr = *(const uint2*)&k2[((long)bh * Ln + l) * 64 + c4];
            uint2 vr = *(const uint2*)&qkv[((long)(b * Ln + l)) * 1536 + 1024 + h * 64 + c4];
            float2 k0 = __half22float2(*(__half2*)&kr.x);
            float2 k1 = __half22float2(*(__half2*)&kr.y);
            float2 v0 = __half22float2(*(__half2*)&vr.x);
            float2 v1 = __half22float2(*(__half2*)&vr.y);
            ks[r][c4] = k0.x; ks[r][c4+1] = k0.y; ks[r][c4+2] = k1.x; ks[r][c4+3] = k1.y;
            vs[r][c4] = v0.x; vs[r][c4+1] = v0.y; vs[r][c4+2] = v1.x; vs[r][c4+3] = v1.y;
        }
        __syncthreads();
        #pragma unroll
        for (int l = 0; l < 32; l++) {
            float4 kr = *(const float4*)&ks[l][d0];
            float4 vr = *(const float4*)&vs[l][e0];
            float k_[4] = {kr.x, kr.y, kr.z, kr.w};
            float v_[4] = {vr.x, vr.y, vr.z, vr.w};
            if (kmwriter) {
                ksum[0] += k_[0]; ksum[1] += k_[1]; ksum[2] += k_[2]; ksum[3] += k_[3];
            }
            #pragma unroll
            for (int i = 0; i < 4; i++)
                #pragma unroll
                for (int j = 0; j < 4; j++)
                    acc[i][j] += k_[i] * v_[j];
        }
        __syncthreads();
    }
    __half* dst = part + ((long)chunk * BHn + bh) * (Dn * Dn);
    #pragma unroll
    for (int i = 0; i < 4; i++) {
        __half2 p0 = __floats2half2_rn(acc[i][0], acc[i][1]);
        __half2 p1 = __floats2half2_rn(acc[i][2], acc[i][3]);
        uint2 w; *(__half2*)&w.x = p0; *(__half2*)&w.y = p1;
        *(uint2*)&dst[(d0 + i) * 64 + e0] = w;
    }
    if (kmwriter) {
        float* kd = kmpart + ((long)chunk * BHn + bh) * Dn + d0;
        kd[0] = ksum[0]; kd[1] = ksum[1]; kd[2] = ksum[2]; kd[3] = ksum[3];
    }
}

// ---------------- reduce partials -> kvT2 (half, [bh][72][64]) ----------------
__global__ void kv_reduce_kernel(const __half* __restrict__ part, const float* __restrict__ kmpart,
                                 __half* __restrict__ kvT2) {
    int i = blockIdx.x * blockDim.x + threadIdx.x;
    if (i < BHn * 4096) {
        int bh = i >> 12;
        int de = i & 4095;
        int d = de >> 6, e = de & 63;
        float s = 0.0f;
        #pragma unroll
        for (int c = 0; c < KVCHUNKS; c++) s += __half2float(part[(long)c * (BHn * 4096) + i]);
        kvT2[(long)bh * 4608 + e * 64 + d] = __float2half_rn(s * (1.0f / Ln));
    } else if (i < BHn * 4096 + BHn * 64) {
        int j = i - BHn * 4096;
        int bh = j >> 6, d = j & 63;
        float s = 0.0f;
        #pragma unroll
        for (int c = 0; c < KVCHUNKS; c++) s += kmpart[(long)c * (BHn * 64) + j];
        kvT2[(long)bh * 4608 + 4096 + d] = __float2half_rn(s * (1.0f / Ln));
    } else if (i < BHn * 4096 + BHn * 64 + BHn * 448) {
        int j = i - BHn * 4096 - BHn * 64;
        int bh = j / 448, rr = j % 448;
        kvT2[(long)bh * 4608 + 4160 + rr] = __ushort_as_half((unsigned short)0);
    }
}

// ---------------- attention output via mma: xbufh = x + (q2@kvT^T) * z ----------------
__global__ void attn_out_kernel(const __half* __restrict__ q2, const __half* __restrict__ kvT2,
                                const float* __restrict__ x, __half* __restrict__ xbuf) {
    int bh = blockIdx.x, b = bh >> 3, h = bh & 7;
    int lbase = blockIdx.y * 128;
    __shared__ __align__(16) __half qs[128 * 64];
    __shared__ __align__(16) __half bs[72 * 64];
    int t = threadIdx.x, wid = t >> 5, lane = t & 31;
    int g = lane >> 2, tig = lane & 3;
    #pragma unroll
    for (int i = 0; i < 4; i++) {
        int idx = t + i * 256;
        int r = idx >> 3, c = idx & 7;
        *(uint4*)((char*)qs + r * 128 + ((c ^ (r & 7)) << 4)) =
            *(const uint4*)&q2[((long)bh * Ln + lbase + r) * 64 + c * 8];
    }
    #pragma unroll
    for (int i = 0; i < 3; i++) {
        int idx = t + i * 256;
        if (idx < 576) {
            int r = idx >> 3, c = idx & 7;
            *(uint4*)((char*)bs + r * 128 + ((c ^ (r & 7)) << 4)) =
                *(const uint4*)&kvT2[(long)bh * 4608 + r * 64 + c * 8];
        }
    }
    __syncthreads();
    uint32_t sq = smem_u32(qs), sbm = smem_u32(bs);
    uint32_t m = (uint32_t)(wid * 16 + (lane & 15));
    uint32_t aRow = m * 128, aSw = m & 7, cHiA = (uint32_t)(lane >> 4);
    float acc[9][4] = {};
    #pragma unroll
    for (int kb = 0; kb < 4; kb++) {
        uint32_t a[4];
        ldsm4(a, sq + aRow + ((((uint32_t)(2 * kb) | cHiA) ^ aSw) << 4));
        #pragma unroll
        for (int np = 0; np < 4; np++) {
            uint32_t r = (uint32_t)(np * 16 + ((lane >> 4) << 3) + (lane & 7));
            uint32_t ch = (uint32_t)(2 * kb) | (uint32_t)((lane >> 3) & 1);
            uint32_t bb[4];
            ldsm4(bb, sbm + r * 128 + ((ch ^ (r & 7)) << 4));
            uint32_t b0[2] = {bb[0], bb[1]}, b1[2] = {bb[2], bb[3]};
            mma_f16(acc[2 * np],     a, b0);
            mma_f16(acc[2 * np + 1], a, b1);
        }
        {
            uint32_t r = (uint32_t)(64 + (lane & 7));
            uint32_t ch = (uint32_t)(2 * kb) | (uint32_t)((lane >> 3) & 1);
            uint32_t bb[2];
            ldsm2(bb, sbm + r * 128 + ((ch ^ (r & 7)) << 4));
            mma_f16(acc[8], a, bb);
        }
    }
    float zg  = __shfl_sync(0xFFFFFFFFu, acc[8][0], lane & ~3) + 1e-6f;
    float zg8 = __shfl_sync(0xFFFFFFFFu, acc[8][2], lane & ~3) + 1e-6f;
    zg = 1.0f / zg;
    zg8 = 1.0f / zg8;
    int row0 = lbase + wid * 16 + g;
    #pragma unroll
    for (int nt = 0; nt < 8; nt++) {
        int col = h * 64 + nt * 8 + tig * 2;
        long off0 = (long)(b * Ln + row0) * Cn + col;
        long off1 = off0 + 8L * Cn;
        float2 x0 = *(const float2*)&x[off0];
        float2 x1 = *(const float2*)&x[off1];
        *(__half2*)&xbuf[off0] = __floats2half2_rn(x0.x + acc[nt][0] * zg,  x0.y + acc[nt][1] * zg);
        *(__half2*)&xbuf[off1] = __floats2half2_rn(x1.x + acc[nt][2] * zg8, x1.y + acc[nt][3] * zg8);
    }
}

// ================= fp16 mma.sync GEMM, K-chunk 64, 3-stage =================
#define GSTG 32768
#define GSM  (3 * GSTG)

template<int EPI, int CONVA>
__global__ void __launch_bounds__(256, 2)
gemm_h(const __half* __restrict__ A, const __half* __restrict__ Bt,
       const float* __restrict__ bias, const void* __restrict__ resv,
       void* __restrict__ Cv, int M, int N, int K) {
    extern __shared__ char smraw[];
    uint32_t sb = smem_u32(smraw);
    int t = threadIdx.x, wid = t >> 5, lane = t & 31;
    int g = lane >> 2, tig = lane & 3;
    int bm = blockIdx.y * 128, bn = blockIdx.x * 128;
    int wm = (wid >> 2) * 64, wn = (wid & 3) * 32;

    const __half* aG[4]; const __half* bG[4]; uint32_t offA[4], offB[4];
    int rs[4], cs[4];
    #pragma unroll
    for (int i = 0; i < 4; i++) {
        int idx = t + i * 256;
        int r = idx >> 3;
        int c = idx & 7;
        rs[i] = r; cs[i] = c;
        uint32_t off = (uint32_t)r * 128 + (uint32_t)((c ^ (r & 7)) << 4);
        offA[i] = off;
        offB[i] = off + 16384;
        if (!CONVA) aG[i] = A + (long)(bm + r) * K + c * 8;
        bG[i] = Bt + (long)(bn + r) * K + c * 8;
    }

    uint32_t aRow[4], aSw[4];
    #pragma unroll
    for (int mt = 0; mt < 4; mt++) {
        uint32_t m = wm + mt * 16 + (lane & 15);
        aRow[mt] = m * 128;
        aSw[mt] = m & 7;
    }
    uint32_t cHiA = lane >> 4;
    uint32_t bRow[2], bSw[2];
    #pragma unroll
    for (int np = 0; np < 2; np++) {
        uint32_t n = wn + np * 16 + ((lane >> 4) << 3) + (lane & 7);
        bRow[np] = n * 128 + 16384;
        bSw[np] = n & 7;
    }
    uint32_t cHiB = (lane >> 3) & 1;

    int nk = K >> 6;

    auto loadA_conv = [&](uint32_t stb, int kt) {
        int tap = kt >> 3;
        int kin = (kt & 7) * 64;
        #pragma unroll
        for (int i = 0; i < 4; i++) {
            long row = bm + rs[i];
            int l = (int)(row & (Ln - 1));
            bool valid = (unsigned)(l + tap - 1) < (unsigned)Ln;
            const __half* src = valid ? (A + (row + tap - 1) * Cn + kin + cs[i] * 8) : A;
            cpasync16z(stb + offA[i], src, valid ? 16u : 0u);
        }
    };

    #pragma unroll
    for (int s = 0; s < 2; s++) {
        uint32_t stb = sb + s * GSTG;
        if (CONVA) loadA_conv(stb, s);
        else {
            #pragma unroll
            for (int i = 0; i < 4; i++) cpasync16(stb + offA[i], aG[i] + s * 64);
        }
        #pragma unroll
        for (int i = 0; i < 4; i++) cpasync16(stb + offB[i], bG[i] + s * 64);
        CP_COMMIT();
    }
    CP_WAIT1();
    __syncthreads();

    float acc[4][4][4] = {};

    for (int kt = 0; kt < nk; kt++) {
        if (kt + 2 < nk) {
            uint32_t stb = sb + ((kt + 2) % 3) * GSTG;
            if (CONVA) loadA_conv(stb, kt + 2);
            else {
                #pragma unroll
                for (int i = 0; i < 4; i++) cpasync16(stb + offA[i], aG[i] + (long)(kt + 2) * 64);
            }
            #pragma unroll
            for (int i = 0; i < 4; i++) cpasync16(stb + offB[i], bG[i] + (long)(kt + 2) * 64);
        }
        CP_COMMIT();

        uint32_t stb = sb + (kt % 3) * GSTG;
        #pragma unroll
        for (int kb = 0; kb < 4; kb++) {
            uint32_t a[4][4], b[4][2];
            #pragma unroll
            for (int mt = 0; mt < 4; mt++) {
                uint32_t addr = stb + aRow[mt] + ((((uint32_t)(2 * kb) | cHiA) ^ aSw[mt]) << 4);
                ldsm4(a[mt], addr);
            }
            #pragma unroll
            for (int np = 0; np < 2; np++) {
                uint32_t bb[4];
                uint32_t addr = stb + bRow[np] + ((((uint32_t)(2 * kb) | cHiB) ^ bSw[np]) << 4);
                ldsm4(bb, addr);
                b[2*np][0] = bb[0]; b[2*np][1] = bb[1];
                b[2*np+1][0] = bb[2]; b[2*np+1][1] = bb[3];
            }
            #pragma unroll
            for (int mt = 0; mt < 4; mt++)
                #pragma unroll
                for (int nt = 0; nt < 4; nt++)
                    mma_f16(acc[mt][nt], a[mt], b[nt]);
        }

        CP_WAIT1();
        __syncthreads();
    }

    // ---- epilogue ----
    if (EPI == 3) {
        float* sg = (float*)smraw;
        #pragma unroll
        for (int mt = 0; mt < 4; mt++) {
            int r0 = wm + mt * 16 + g;
            #pragma unroll
            for (int nt = 0; nt < 4; nt++) {
                int col = wn + nt * 8 + tig * 2;
                float b0 = bias[bn + col], b1 = bias[bn + col + 1];
                float vv0 = acc[mt][nt][0] + b0, gg0 = acc[mt][nt][1] + b1;
                float vv1 = acc[mt][nt][2] + b0, gg1 = acc[mt][nt][3] + b1;
                int cp = col >> 1;
                sg[r0 * 68 + cp]       = vv0 / (1.0f + __expf(-gg0));
                sg[(r0 + 8) * 68 + cp] = vv1 / (1.0f + __expf(-gg1));
            }
        }
        __syncthreads();
        int cpb = bn >> 1;
        __half* X = (__half*)Cv;
        const __half* R = (const __half*)resv;
        #pragma unroll
        for (int i = 0; i < 8; i++) {
            int j = t + i * 256;
            int r = j >> 4, c4 = j & 15;
            long off = (long)(bm + r) * Cn + cpb + c4 * 4;
            uint2 xraw = *(uint2*)(X + off);
            uint2 spraw = *(const uint2*)(R + off);
            float2 x0 = __half22float2(*(__half2*)&xraw.x);
            float2 x1 = __half22float2(*(__half2*)&xraw.y);
            float2 s0 = __half22float2(*(__half2*)&spraw.x);
            float2 s1 = __half22float2(*(__half2*)&spraw.y);
            float4 gv = *(float4*)&sg[r * 68 + c4 * 4];
            uint2 outp;
            *(__half2*)&outp.x = __floats2half2_rn(x0.x + s0.x + gv.x, x0.y + s0.y + gv.y);
            *(__half2*)&outp.y = __floats2half2_rn(x1.x + s1.x + gv.z, x1.y + s1.y + gv.w);
            *(uint2*)(X + off) = outp;
        }
        return;
    }

    #pragma unroll
    for (int mt = 0; mt < 4; mt++) {
        int row = bm + wm + mt * 16 + g;
        #pragma unroll
        for (int nt = 0; nt < 4; nt++) {
            int col = bn + wn + nt * 8 + tig * 2;
            float b0 = bias[col], b1 = bias[col + 1];
            float v00 = acc[mt][nt][0] + b0;
            float v01 = acc[mt][nt][1] + b1;
            float v10 = acc[mt][nt][2] + b0;
            float v11 = acc[mt][nt][3] + b1;
            if (EPI == 1) {
                v00 = 0.5f * v00 * (1.0f + erff(v00 * 0.70710678118654752f));
                v01 = 0.5f * v01 * (1.0f + erff(v01 * 0.70710678118654752f));
                v10 = 0.5f * v10 * (1.0f + erff(v10 * 0.70710678118654752f));
                v11 = 0.5f * v11 * (1.0f + erff(v11 * 0.70710678118654752f));
                __half2* C = (__half2*)Cv;
                C[((long)row * N + col) >> 1]       = __floats2half2_rn(v00, v01);
                C[((long)(row + 8) * N + col) >> 1] = __floats2half2_rn(v10, v11);
            } else if (EPI == 4) {
                __half2* C = (__half2*)Cv;
                C[((long)row * N + col) >> 1]       = __floats2half2_rn(v00, v01);
                C[((long)(row + 8) * N + col) >> 1] = __floats2half2_rn(v10, v11);
            } else {  // EPI == 2
                const __half2* R = (const __half2*)resv;
                float2 f0 = __half22float2(R[((long)row * N + col) >> 1]);
                float2 f1 = __half22float2(R[((long)(row + 8) * N + col) >> 1]);
                v00 += f0.x; v01 += f0.y;
                v10 += f1.x; v11 += f1.y;
                float* C = (float*)Cv;
                float2 p0 = {v00, v01}, p1 = {v10, v11};
                *(float2*)(C + (long)row * N + col)       = p0;
                *(float2*)(C + (long)(row + 8) * N + col) = p1;
            }
        }
    }
}

// ---------------- host launcher ----------------
extern "C" void kernel_launch(void* const* d_in, const int* in_sizes, int n_in,
                              void* d_out, int out_size) {
    const float* x      = (const float*)d_in[0];
    const float* g1     = (const float*)d_in[1];
    const float* b1     = (const float*)d_in[2];
    const float* qk_w   = (const float*)d_in[3];
    const float* qk_b   = (const float*)d_in[4];
    const float* v_w    = (const float*)d_in[5];
    const float* v_b    = (const float*)d_in[6];
    const float* lepe_w = (const float*)d_in[7];
    const float* lepe_b = (const float*)d_in[8];
    const float* g2     = (const float*)d_in[9];
    const float* b2     = (const float*)d_in[10];
    const float* spn_g  = (const float*)d_in[11];
    const float* spn_b  = (const float*)d_in[12];
    const float* sp_cw  = (const float*)d_in[13];
    const float* sp_cb  = (const float*)d_in[14];
    const float* g3     = (const float*)d_in[15];
    const float* b3     = (const float*)d_in[16];
    const float* w1     = (const float*)d_in[17];
    const float* bb1    = (const float*)d_in[18];
    const float* w2     = (const float*)d_in[19];
    const float* bb2    = (const float*)d_in[20];
    float* out = (float*)d_out;

    float *kmpart, *bias2, *bias3;
    __half *xbufh, *lnh, *qkvh, *q2h, *k2h, *kvpart, *kvT2h, *spinh, *hb, *ffnh;
    __half *qkvTh, *w1Th, *w2Th, *wtT2h;
    cudaGetSymbolAddress((void**)&xbufh,  g_xbufh);
    cudaGetSymbolAddress((void**)&lnh,    g_lnh);
    cudaGetSymbolAddress((void**)&qkvh,   g_qkvh);
    cudaGetSymbolAddress((void**)&q2h,    g_q2h);
    cudaGetSymbolAddress((void**)&k2h,    g_k2h);
    cudaGetSymbolAddress((void**)&kvpart, g_kvpart);
    cudaGetSymbolAddress((void**)&kmpart, g_kmpart);
    cudaGetSymbolAddress((void**)&kvT2h,  g_kvT2h);
    cudaGetSymbolAddress((void**)&spinh,  g_spinh);
    cudaGetSymbolAddress((void**)&hb,     g_hb);
    cudaGetSymbolAddress((void**)&ffnh,   g_ffnh);
    cudaGetSymbolAddress((void**)&qkvTh,  g_qkvTh);
    cudaGetSymbolAddress((void**)&w1Th,   g_w1Th);
    cudaGetSymbolAddress((void**)&w2Th,   g_w2Th);
    cudaGetSymbolAddress((void**)&wtT2h,  g_wtT2h);
    cudaGetSymbolAddress((void**)&bias2,  g_bias2);
    cudaGetSymbolAddress((void**)&bias3,  g_bias3);

    cudaFuncSetAttribute((const void*)gemm_h<4,0>, cudaFuncAttributeMaxDynamicSharedMemorySize, GSM);
    cudaFuncSetAttribute((const void*)gemm_h<3,1>, cudaFuncAttributeMaxDynamicSharedMemorySize, GSM);
    cudaFuncSetAttribute((const void*)gemm_h<1,0>, cudaFuncAttributeMaxDynamicSharedMemorySize, GSM);
    cudaFuncSetAttribute((const void*)gemm_h<2,0>, cudaFuncAttributeMaxDynamicSharedMemorySize, GSM);

    prep_weights_kernel<<<(int)((PW_TOT + 255) / 256), 256>>>(
        qk_w, v_w, w1, w2, sp_cw, qk_b, v_b, sp_cb,
        qkvTh, w1Th, w2Th, wtT2h, bias2, bias3);

    // Block 1: xbufh = x + attn(LN1(x))
    ln_h_kernel<<<BLn, 128>>>(x, g1, b1, lnh);
    gemm_h<4,0><<<dim3(1536 / 128, BLn / 128), 256, GSM>>>(lnh, qkvTh, bias3, nullptr, qkvh, BLn, 1536, Cn);
    qk_post_kernel<<<dim3(BHn, Ln / 64), 256>>>(qkvh, lepe_w, lepe_b, q2h, k2h);
    kv_kernel<<<dim3(BHn, KVCHUNKS), 256>>>(k2h, qkvh, kvpart, kmpart);
    kv_reduce_kernel<<<(BHn * 4096 + BHn * 64 + BHn * 448 + 255) / 256, 256>>>(kvpart, kmpart, kvT2h);
    attn_out_kernel<<<dim3(BHn, Ln / 128), 256>>>(q2h, kvT2h, x, xbufh);

    // Block 2: gated conv state path
    ln2ln3_kernel<<<BLn, 128>>>(xbufh, g2, b2, spn_g, spn_b, spinh, hb);
    gemm_h<3,1><<<dim3(1024 / 128, BLn / 128), 256, GSM>>>(hb, wtT2h, bias2, spinh, xbufh, BLn, 1024, 3 * Cn);

    // Block 3: FFN
    ln_hh_kernel<<<BLn, 128>>>(xbufh, g3, b3, lnh);
    gemm_h<1,0><<<dim3(FFn / 128, BLn / 128), 256, GSM>>>(lnh, w1Th, bb1, nullptr, ffnh, BLn, FFn, Cn);
    gemm_h<2,0><<<dim3(512 / 128, BLn / 128), 256, GSM>>>(ffnh, w2Th, bb2, xbufh, out, BLn, 512, FFn);
}